// round 10
// baseline (speedup 1.0000x reference)
#include <cuda_runtime.h>
#include <cuda_fp16.h>
#include <cstdint>

// Problem constants (fixed shapes per reference setup_inputs)
#define N_IMG 8
#define C_CH  256
#define H_IN  100
#define W_IN  100
#define HW_IN (H_IN*W_IN)            // 10000
#define OUT_H 7
#define OUT_W 7
#define SR    2
#define SPATIAL_SCALE 0.25f
#define NBINS (OUT_H*OUT_W)          // 49
#define NSAMP (OUT_H*SR)             // 14
#define NPAIR (NSAMP*NSAMP)          // 196
#define OUT_PER_ROI (C_CH*NBINS)     // 12544 floats
#define CH_CHUNK 128                 // channels per block
#define CHUNK_FLOATS (CH_CHUNK * NBINS)  // 6272 floats
#define OCT_ROW 400                  // padded staging row (floats) per channel-octet

// NHWC fp16 scratch: 8*100*100*256 halves = 40.96 MB (static device array)
__device__ __half g_nhwc[N_IMG * HW_IN * C_CH];

// ---------------------------------------------------------------------------
// Kernel 1: NCHW fp32 -> NHWC fp16 transpose (R9 version, unchanged).
// ---------------------------------------------------------------------------
__global__ __launch_bounds__(256) void nchw_to_nhwc_kernel(const float* __restrict__ src) {
    __shared__ float tile[64][65];
    const int n      = blockIdx.z;
    const int cBase  = blockIdx.y * 64;
    const int hwBase = blockIdx.x * 64;
    const int tx = threadIdx.x;          // 0..31
    const int ty = threadIdx.y;          // 0..7

    int hw0 = hwBase + tx * 2;
    if (hw0 < HW_IN) {
        #pragma unroll
        for (int i = 0; i < 8; i++) {
            int c = ty + i * 8;
            float2 v = *(const float2*)(src + ((size_t)n * C_CH + cBase + c) * HW_IN + hw0);
            tile[c][tx * 2 + 0] = v.x;
            tile[c][tx * 2 + 1] = v.y;
        }
    }
    __syncthreads();

    const int c2 = tx * 2;
    #pragma unroll
    for (int i = 0; i < 8; i++) {
        int hwl = ty + i * 8;
        int hw  = hwBase + hwl;
        if (hw < HW_IN) {
            __half2 h = __floats2half2_rn(tile[c2][hwl], tile[c2 + 1][hwl]);
            *(__half2*)(g_nhwc + ((size_t)n * HW_IN + hw) * C_CH + cBase + c2) = h;
        }
    }
}

// ---------------------------------------------------------------------------
// Kernel 2: ROI align, fp16 math, 16B lanes.
//   grid = (K, 2): blockIdx.x = ROI, blockIdx.y = 128-channel chunk.
//   half-warp (16 lanes) = one bin; lane covers 8 channels (one LDG.128 per
//   corner). Bins strided by 16 across half-warps (h=0 also takes bin 48).
// Per sample: 1 LDS.128 offsets + 1 LDS.128 weights + 4 LDG.128 + 16 HFMA2
// + cvt + 8 fp32 FMA (0.25 folded). ~2x fewer memory instructions than R9.
// ---------------------------------------------------------------------------
__global__ __launch_bounds__(256, 4) void roi_align_kernel(
    const float* __restrict__ rois,
    float* __restrict__ out,
    int K)
{
    __shared__ float  s_wy0[NSAMP], s_wy1[NSAMP], s_wx0[NSAMP], s_wx1[NSAMP];
    __shared__ int    s_oy0[NSAMP], s_oy1[NSAMP], s_ox0[NSAMP], s_ox1[NSAMP];
    __shared__ uint4  s_wh[NPAIR];            // 4 broadcast half2 weights/pair
    __shared__ int4   s_o4[NPAIR];            // 4 corner element offsets
    __shared__ float  s_out[16 * OCT_ROW];    // [16 octets][49 bins][8] padded

    const int k   = blockIdx.x;
    const int p   = blockIdx.y;
    const int tid = threadIdx.x;

    if (tid < NSAMP) {
        const float* r = rois + (size_t)k * 5;
        int   b  = (int)r[0];
        float x1 = r[1] * SPATIAL_SCALE;
        float y1 = r[2] * SPATIAL_SCALE;
        float x2 = r[3] * SPATIAL_SCALE;
        float y2 = r[4] * SPATIAL_SCALE;
        float roi_w = fmaxf(x2 - x1, 1.0f);
        float roi_h = fmaxf(y2 - y1, 1.0f);
        float bin_w = roi_w * (1.0f / OUT_W);
        float bin_h = roi_h * (1.0f / OUT_H);
        float t = ((float)tid + 0.5f) * (1.0f / SR);

        float gy = y1 + bin_h * t;
        float vy = (gy >= -1.0f && gy <= (float)H_IN) ? 1.0f : 0.0f;
        float y  = fminf(fmaxf(gy, 0.0f), (float)(H_IN - 1));
        float yl = floorf(y);
        int y0   = (int)yl;
        int y1i  = min(y0 + 1, H_IN - 1);
        float ly = y - yl;
        s_wy0[tid] = vy * (1.0f - ly);
        s_wy1[tid] = vy * ly;
        s_oy0[tid] = (b * HW_IN + y0  * W_IN) * C_CH;
        s_oy1[tid] = (b * HW_IN + y1i * W_IN) * C_CH;

        float gx = x1 + bin_w * t;
        float vx = (gx >= -1.0f && gx <= (float)W_IN) ? 1.0f : 0.0f;
        float x  = fminf(fmaxf(gx, 0.0f), (float)(W_IN - 1));
        float xl = floorf(x);
        int x0   = (int)xl;
        int x1i  = min(x0 + 1, W_IN - 1);
        float lx = x - xl;
        s_wx0[tid] = vx * (1.0f - lx);
        s_wx1[tid] = vx * lx;
        s_ox0[tid] = x0  * C_CH;
        s_ox1[tid] = x1i * C_CH;
    }
    __syncthreads();

    if (tid < NPAIR) {
        int iy = tid / NSAMP;
        int ix = tid - iy * NSAMP;
        float wy0 = s_wy0[iy], wy1 = s_wy1[iy];
        float wx0 = s_wx0[ix], wx1 = s_wx1[ix];
        __half2 h00 = __float2half2_rn(wy0 * wx0);
        __half2 h01 = __float2half2_rn(wy0 * wx1);
        __half2 h10 = __float2half2_rn(wy1 * wx0);
        __half2 h11 = __float2half2_rn(wy1 * wx1);
        uint4 w;
        w.x = *(uint32_t*)&h00; w.y = *(uint32_t*)&h01;
        w.z = *(uint32_t*)&h10; w.w = *(uint32_t*)&h11;
        s_wh[tid] = w;
        int oy0 = s_oy0[iy], oy1 = s_oy1[iy];
        int ox0 = s_ox0[ix], ox1 = s_ox1[ix];
        s_o4[tid] = make_int4(oy0 + ox0, oy0 + ox1, oy1 + ox0, oy1 + ox1);
    }
    __syncthreads();

    const int h16    = tid >> 4;         // half-warp id 0..15 (one bin each)
    const int lane16 = tid & 15;         // channel octet (8 ch, 16B)
    const __half* srcp = g_nhwc + (p * CH_CHUNK + lane16 * 8);

    for (int bin = h16; bin < NBINS; bin += 16) {
        int ph = bin / OUT_W;
        int pw = bin - ph * OUT_W;
        int i00 = (2 * ph) * NSAMP + 2 * pw;
        const int idx[4] = {i00, i00 + 1, i00 + NSAMP, i00 + NSAMP + 1};

        float4 a0 = make_float4(0.f, 0.f, 0.f, 0.f);
        float4 a1 = make_float4(0.f, 0.f, 0.f, 0.f);

        #pragma unroll
        for (int s = 0; s < 4; s++) {
            int4  o = s_o4[idx[s]];
            uint4 w = s_wh[idx[s]];
            uint4 d0 = *(const uint4*)(srcp + o.x);
            uint4 d1 = *(const uint4*)(srcp + o.y);
            uint4 d2 = *(const uint4*)(srcp + o.z);
            uint4 d3 = *(const uint4*)(srcp + o.w);
            __half2 w00 = *(__half2*)&w.x, w01 = *(__half2*)&w.y;
            __half2 w10 = *(__half2*)&w.z, w11 = *(__half2*)&w.w;
            const __half2* v0 = (const __half2*)&d0;
            const __half2* v1 = (const __half2*)&d1;
            const __half2* v2 = (const __half2*)&d2;
            const __half2* v3 = (const __half2*)&d3;
            float* acc = (float*)&a0;    // a0,a1 contiguous? use explicit below
            #pragma unroll
            for (int j = 0; j < 4; j++) {
                __half2 r = __hmul2(w00, v0[j]);
                r = __hfma2(w01, v1[j], r);
                r = __hfma2(w10, v2[j], r);
                r = __hfma2(w11, v3[j], r);
                float2 f = __half22float2(r);
                if (j == 0) { a0.x = fmaf(0.25f, f.x, a0.x); a0.y = fmaf(0.25f, f.y, a0.y); }
                if (j == 1) { a0.z = fmaf(0.25f, f.x, a0.z); a0.w = fmaf(0.25f, f.y, a0.w); }
                if (j == 2) { a1.x = fmaf(0.25f, f.x, a1.x); a1.y = fmaf(0.25f, f.y, a1.y); }
                if (j == 3) { a1.z = fmaf(0.25f, f.x, a1.z); a1.w = fmaf(0.25f, f.y, a1.w); }
            }
            (void)acc;
        }
        float* sb = &s_out[lane16 * OCT_ROW + bin * 8];
        *(float4*)(sb + 0) = a0;
        *(float4*)(sb + 4) = a1;
    }
    __syncthreads();

    // Writeback: out element e = c*49 + bin within this chunk;
    // staged at [(c>>3)*OCT_ROW + bin*8 + (c&7)]. Coalesced 4B stores.
    float* ob = out + (size_t)k * OUT_PER_ROI + p * CHUNK_FLOATS;
    #pragma unroll 4
    for (int e = tid; e < CHUNK_FLOATS; e += 256) {
        int c   = e / NBINS;
        int bin = e - c * NBINS;
        ob[e] = s_out[(c >> 3) * OCT_ROW + bin * 8 + (c & 7)];
    }
}

extern "C" void kernel_launch(void* const* d_in, const int* in_sizes, int n_in,
                              void* d_out, int out_size) {
    const float* input = (const float*)d_in[0];  // (8,256,100,100) f32
    const float* rois  = (const float*)d_in[1];  // (K,5) f32
    float* out = (float*)d_out;                  // (K,256,7,7) f32
    int K = in_sizes[1] / 5;

    dim3 tgrid((HW_IN + 63) / 64, C_CH / 64, N_IMG);
    dim3 tblock(32, 8);
    nchw_to_nhwc_kernel<<<tgrid, tblock>>>(input);

    dim3 rgrid(K, 2);
    roi_align_kernel<<<rgrid, 256>>>(rois, out, K);
}